// round 2
// baseline (speedup 1.0000x reference)
#include <cuda_runtime.h>

#define NN 100000
#define EE 1600000
#define HH 128

// ---------- scratch (static device arrays; no allocation allowed) ----------
__device__ float g_res[NN * HH];     // residual = x@Wr + br
__device__ float g_h[NN * HH];       // GEMM output per layer
__device__ float g_y[NN * HH];       // post-aggregation activation
__device__ float g_dinv[NN];         // D^{-1/2}
__device__ int   g_deg[NN];          // in-degree incl. self loop
__device__ int   g_rowstart[NN + 1]; // CSR row pointers (real edges only)
__device__ int   g_cursor[NN];       // fill cursors
__device__ int   g_csr_src[EE];      // CSR column (src node)
__device__ float g_csr_w[EE];        // precomputed dinv[src]*dinv[dst]

// ---------- degree / norm ----------
__global__ void k_deg_init() {
    int i = blockIdx.x * blockDim.x + threadIdx.x;
    if (i < NN) g_deg[i] = 1;  // self loop
}

__global__ void k_count(const int* __restrict__ dst) {
    int e = blockIdx.x * blockDim.x + threadIdx.x;
    if (e < EE) atomicAdd(&g_deg[dst[e]], 1);
}

__global__ void k_dinv() {
    int i = blockIdx.x * blockDim.x + threadIdx.x;
    if (i < NN) g_dinv[i] = rsqrtf((float)g_deg[i]);
}

// ---------- single-block exclusive prefix scan over (deg-1) ----------
__global__ void k_scan() {
    __shared__ int ssum[1024];
    const int T = 1024;
    const int C = (NN + T - 1) / T;  // 98
    int t = threadIdx.x;
    int beg = t * C;
    int end = min(beg + C, NN);
    int s = 0;
    for (int i = beg; i < end; i++) s += g_deg[i] - 1;
    ssum[t] = s;
    __syncthreads();
    // Hillis-Steele inclusive scan
    for (int off = 1; off < T; off <<= 1) {
        int v = (t >= off) ? ssum[t - off] : 0;
        __syncthreads();
        ssum[t] += v;
        __syncthreads();
    }
    int run = ssum[t] - s;  // exclusive offset
    for (int i = beg; i < end; i++) {
        g_rowstart[i] = run;
        g_cursor[i]   = run;
        run += g_deg[i] - 1;
    }
    if (t == T - 1) g_rowstart[NN] = run;  // == EE
}

// ---------- CSR fill ----------
__global__ void k_fill(const int* __restrict__ src, const int* __restrict__ dst) {
    int e = blockIdx.x * blockDim.x + threadIdx.x;
    if (e >= EE) return;
    int s = src[e];
    int d = dst[e];
    int pos = atomicAdd(&g_cursor[d], 1);
    g_csr_src[pos] = s;
    g_csr_w[pos]   = g_dinv[s] * g_dinv[d];
}

// ---------- GEMM: C[M,128] = A[M,128] @ W[128,128] (+ bias) ----------
// BM=64 rows/block, 256 threads, each thread computes 8 rows x 4 cols.
__global__ void __launch_bounds__(256) k_gemm(const float* __restrict__ A,
                                              const float* __restrict__ W,
                                              const float* __restrict__ bias,
                                              float* __restrict__ C, int M) {
    __shared__ float sX[64][32];
    __shared__ float sW[32][128];

    int tid = threadIdx.x;
    int tx = tid & 31;   // column group: cols tx*4 .. tx*4+3
    int ty = tid >> 5;   // row group: rows ty, ty+8, ..., ty+56
    int row0 = blockIdx.x * 64;

    float acc[8][4];
#pragma unroll
    for (int i = 0; i < 8; i++)
#pragma unroll
        for (int j = 0; j < 4; j++) acc[i][j] = 0.f;

    for (int kk = 0; kk < 128; kk += 32) {
        // stage A tile [64 x 32]
#pragma unroll
        for (int e = tid; e < 64 * 32; e += 256) {
            int r = e >> 5, c = e & 31;
            int gr = row0 + r;
            sX[r][c] = (gr < M) ? A[gr * 128 + kk + c] : 0.f;
        }
        // stage W tile [32 x 128]
#pragma unroll
        for (int e = tid; e < 32 * 128; e += 256) {
            int r = e >> 7, c = e & 127;
            sW[r][c] = W[(kk + r) * 128 + c];
        }
        __syncthreads();

#pragma unroll
        for (int k = 0; k < 32; k++) {
            float4 wv = *(const float4*)&sW[k][tx * 4];
#pragma unroll
            for (int i = 0; i < 8; i++) {
                float xv = sX[ty + i * 8][k];
                acc[i][0] += xv * wv.x;
                acc[i][1] += xv * wv.y;
                acc[i][2] += xv * wv.z;
                acc[i][3] += xv * wv.w;
            }
        }
        __syncthreads();
    }

    float4 bv = make_float4(0.f, 0.f, 0.f, 0.f);
    if (bias) bv = *(const float4*)&bias[tx * 4];
#pragma unroll
    for (int i = 0; i < 8; i++) {
        int gr = row0 + ty + i * 8;
        if (gr < M) {
            float4 o;
            o.x = acc[i][0] + bv.x;
            o.y = acc[i][1] + bv.y;
            o.z = acc[i][2] + bv.z;
            o.w = acc[i][3] + bv.w;
            *(float4*)&C[gr * 128 + tx * 4] = o;
        }
    }
}

// ---------- aggregation + epilogue: one warp per node ----------
// out[i] = relu( sum_{j in N(i)} w_j * h[src_j] + dinv[i]^2 * h[i] + bias ) [+ res[i]]
__global__ void __launch_bounds__(256) k_agg(const float* __restrict__ h,
                                             const float* __restrict__ bias,
                                             const float* __restrict__ res,
                                             float* __restrict__ out) {
    int gw = (blockIdx.x * blockDim.x + threadIdx.x) >> 5;
    int lane = threadIdx.x & 31;
    if (gw >= NN) return;
    int i = gw;

    float di = g_dinv[i];
    float wself = di * di;
    const float4* hrow = (const float4*)&h[(size_t)i * 128];
    float4 acc = hrow[lane];
    acc.x *= wself; acc.y *= wself; acc.z *= wself; acc.w *= wself;

    int b = g_rowstart[i];
    int e = g_rowstart[i + 1];
    for (int j = b; j < e; j++) {
        int s   = g_csr_src[j];
        float w = g_csr_w[j];
        float4 v = ((const float4*)&h[(size_t)s * 128])[lane];
        acc.x += v.x * w;
        acc.y += v.y * w;
        acc.z += v.z * w;
        acc.w += v.w * w;
    }

    float4 bb = ((const float4*)bias)[lane];
    float4 o;
    o.x = fmaxf(acc.x + bb.x, 0.f);
    o.y = fmaxf(acc.y + bb.y, 0.f);
    o.z = fmaxf(acc.z + bb.z, 0.f);
    o.w = fmaxf(acc.w + bb.w, 0.f);
    if (res) {
        float4 rv = ((const float4*)&res[(size_t)i * 128])[lane];
        o.x += rv.x; o.y += rv.y; o.z += rv.z; o.w += rv.w;
    }
    ((float4*)&out[(size_t)i * 128])[lane] = o;
}

// ---------- host launcher ----------
extern "C" void kernel_launch(void* const* d_in, const int* in_sizes, int n_in,
                              void* d_out, int out_size) {
    const float* x  = (const float*)d_in[0];
    const int*   ei = (const int*)d_in[1];
    const float* W0 = (const float*)d_in[2];
    const float* b0 = (const float*)d_in[3];
    const float* W1 = (const float*)d_in[4];
    const float* b1 = (const float*)d_in[5];
    const float* W2 = (const float*)d_in[6];
    const float* b2 = (const float*)d_in[7];
    const float* Wr = (const float*)d_in[8];
    const float* br = (const float*)d_in[9];
    float* out = (float*)d_out;

    const int* src = ei;        // edge_index[0]
    const int* dst = ei + EE;   // edge_index[1]

    float *res_p, *h_p, *y_p;
    cudaGetSymbolAddress((void**)&res_p, g_res);
    cudaGetSymbolAddress((void**)&h_p, g_h);
    cudaGetSymbolAddress((void**)&y_p, g_y);

    const int GB = (NN + 63) / 64;        // GEMM blocks
    const int AB = (NN + 7) / 8;          // agg blocks (8 warps/block)
    const int EB = (EE + 255) / 256;
    const int NB = (NN + 255) / 256;

    // graph structure (recomputed each call; no caching)
    k_deg_init<<<NB, 256>>>();
    k_count<<<EB, 256>>>(dst);
    k_dinv<<<NB, 256>>>();
    k_scan<<<1, 1024>>>();
    k_fill<<<EB, 256>>>(src, dst);

    // residual = x @ Wr + br
    k_gemm<<<GB, 256>>>(x, Wr, br, res_p, NN);

    // layer 0
    k_gemm<<<GB, 256>>>(x, W0, nullptr, h_p, NN);
    k_agg<<<AB, 256>>>(h_p, b0, res_p, y_p);

    // layer 1
    k_gemm<<<GB, 256>>>(y_p, W1, nullptr, h_p, NN);
    k_agg<<<AB, 256>>>(h_p, b1, nullptr, y_p);

    // layer 2
    k_gemm<<<GB, 256>>>(y_p, W2, nullptr, h_p, NN);
    k_agg<<<AB, 256>>>(h_p, b2, nullptr, out);
}

// round 3
// speedup vs baseline: 1.3299x; 1.3299x over previous
#include <cuda_runtime.h>

#define NN 100000
#define EE 1600000
#define HH 128

#define SCAN_TPB 256
#define SCAN_NPT 4                       // nodes per thread
#define SCAN_NPB (SCAN_TPB * SCAN_NPT)   // 1024 nodes per block
#define SCAN_NB  ((NN + SCAN_NPB - 1) / SCAN_NPB)  // 98 blocks

// ---------- scratch (static device arrays; no allocation allowed) ----------
__device__ float g_res[NN * HH];     // residual = x@Wr + br
__device__ float g_h[NN * HH];       // GEMM output per layer
__device__ float g_y[NN * HH];       // post-aggregation activation
__device__ float g_dinv[NN];         // D^{-1/2}
__device__ int   g_deg[NN];          // in-degree incl. self loop
__device__ int   g_rowstart[NN + 1]; // CSR row pointers (real edges only)
__device__ int   g_cursor[NN];       // fill cursors
__device__ int   g_csr_src[EE];      // CSR column (src node)
__device__ float g_csr_w[EE];        // precomputed dinv[src]*dinv[dst]
__device__ int   g_blocksum[SCAN_NB];

// ---------- degree / norm ----------
__global__ void k_deg_init() {
    int i = blockIdx.x * blockDim.x + threadIdx.x;
    if (i < NN) g_deg[i] = 1;  // self loop
}

__global__ void k_count(const int* __restrict__ dst) {
    int e = blockIdx.x * blockDim.x + threadIdx.x;
    if (e < EE) atomicAdd(&g_deg[dst[e]], 1);
}

// ---------- scan phase 1: per-block sums of (deg-1); also dinv ----------
__global__ void __launch_bounds__(SCAN_TPB) k_scan1() {
    __shared__ int ssum[SCAN_TPB];
    int t = threadIdx.x;
    int base = blockIdx.x * SCAN_NPB + t * SCAN_NPT;
    int s = 0;
#pragma unroll
    for (int c = 0; c < SCAN_NPT; c++) {
        int i = base + c;
        if (i < NN) {
            int d = g_deg[i];
            g_dinv[i] = rsqrtf((float)d);
            s += d - 1;
        }
    }
    ssum[t] = s;
    __syncthreads();
    // block reduce
    for (int off = SCAN_TPB / 2; off > 0; off >>= 1) {
        if (t < off) ssum[t] += ssum[t + off];
        __syncthreads();
    }
    if (t == 0) g_blocksum[blockIdx.x] = ssum[0];
}

// ---------- scan phase 2: exclusive scan of 98 block sums (1 block) ----------
__global__ void k_scan2() {
    __shared__ int sv[SCAN_NB];
    int t = threadIdx.x;
    if (t < SCAN_NB) sv[t] = g_blocksum[t];
    __syncthreads();
    if (t == 0) {
        int run = 0;
        for (int b = 0; b < SCAN_NB; b++) {
            int v = sv[b];
            g_blocksum[b] = run;   // exclusive
            run += v;
        }
        g_rowstart[NN] = EE;       // sum(deg-1) == EE by construction
    }
}

// ---------- scan phase 3: block-local exclusive scan + write rowstart/cursor --
__global__ void __launch_bounds__(SCAN_TPB) k_scan3() {
    __shared__ int ssum[SCAN_TPB];
    int t = threadIdx.x;
    int base = blockIdx.x * SCAN_NPB + t * SCAN_NPT;
    int local[SCAN_NPT];
    int s = 0;
#pragma unroll
    for (int c = 0; c < SCAN_NPT; c++) {
        int i = base + c;
        int d = (i < NN) ? (g_deg[i] - 1) : 0;
        local[c] = d;
        s += d;
    }
    ssum[t] = s;
    __syncthreads();
    // Hillis-Steele inclusive scan over thread sums
    for (int off = 1; off < SCAN_TPB; off <<= 1) {
        int v = (t >= off) ? ssum[t - off] : 0;
        __syncthreads();
        ssum[t] += v;
        __syncthreads();
    }
    int run = g_blocksum[blockIdx.x] + ssum[t] - s;  // exclusive global offset
#pragma unroll
    for (int c = 0; c < SCAN_NPT; c++) {
        int i = base + c;
        if (i < NN) {
            g_rowstart[i] = run;
            g_cursor[i]   = run;
            run += local[c];
        }
    }
}

// ---------- CSR fill ----------
__global__ void k_fill(const int* __restrict__ src, const int* __restrict__ dst) {
    int e = blockIdx.x * blockDim.x + threadIdx.x;
    if (e >= EE) return;
    int s = src[e];
    int d = dst[e];
    int pos = atomicAdd(&g_cursor[d], 1);
    g_csr_src[pos] = s;
    g_csr_w[pos]   = g_dinv[s] * g_dinv[d];
}

// ---------- GEMM: C[M,128] = A[M,128] @ W[128,128] (+ bias) ----------
// BM=64 rows/block, 256 threads, each thread computes 8 rows x 4 cols.
__global__ void __launch_bounds__(256) k_gemm(const float* __restrict__ A,
                                              const float* __restrict__ W,
                                              const float* __restrict__ bias,
                                              float* __restrict__ C, int M) {
    __shared__ float sX[64][32];
    __shared__ float sW[32][128];

    int tid = threadIdx.x;
    int tx = tid & 31;   // column group: cols tx*4 .. tx*4+3
    int ty = tid >> 5;   // row group: rows ty, ty+8, ..., ty+56
    int row0 = blockIdx.x * 64;

    float acc[8][4];
#pragma unroll
    for (int i = 0; i < 8; i++)
#pragma unroll
        for (int j = 0; j < 4; j++) acc[i][j] = 0.f;

    for (int kk = 0; kk < 128; kk += 32) {
        // stage A tile [64 x 32]
#pragma unroll
        for (int e = tid; e < 64 * 32; e += 256) {
            int r = e >> 5, c = e & 31;
            int gr = row0 + r;
            sX[r][c] = (gr < M) ? A[gr * 128 + kk + c] : 0.f;
        }
        // stage W tile [32 x 128]
#pragma unroll
        for (int e = tid; e < 32 * 128; e += 256) {
            int r = e >> 7, c = e & 127;
            sW[r][c] = W[(kk + r) * 128 + c];
        }
        __syncthreads();

#pragma unroll
        for (int k = 0; k < 32; k++) {
            float4 wv = *(const float4*)&sW[k][tx * 4];
#pragma unroll
            for (int i = 0; i < 8; i++) {
                float xv = sX[ty + i * 8][k];
                acc[i][0] += xv * wv.x;
                acc[i][1] += xv * wv.y;
                acc[i][2] += xv * wv.z;
                acc[i][3] += xv * wv.w;
            }
        }
        __syncthreads();
    }

    float4 bv = make_float4(0.f, 0.f, 0.f, 0.f);
    if (bias) bv = *(const float4*)&bias[tx * 4];
#pragma unroll
    for (int i = 0; i < 8; i++) {
        int gr = row0 + ty + i * 8;
        if (gr < M) {
            float4 o;
            o.x = acc[i][0] + bv.x;
            o.y = acc[i][1] + bv.y;
            o.z = acc[i][2] + bv.z;
            o.w = acc[i][3] + bv.w;
            *(float4*)&C[gr * 128 + tx * 4] = o;
        }
    }
}

// ---------- aggregation + epilogue: one warp per node ----------
// out[i] = relu( sum_{j in N(i)} w_j * h[src_j] + dinv[i]^2 * h[i] + bias ) [+ res[i]]
__global__ void __launch_bounds__(256) k_agg(const float* __restrict__ h,
                                             const float* __restrict__ bias,
                                             const float* __restrict__ res,
                                             float* __restrict__ out) {
    int gw = (blockIdx.x * blockDim.x + threadIdx.x) >> 5;
    int lane = threadIdx.x & 31;
    if (gw >= NN) return;
    int i = gw;

    float di = g_dinv[i];
    float wself = di * di;
    const float4* hrow = (const float4*)&h[(size_t)i * 128];
    float4 acc = hrow[lane];
    acc.x *= wself; acc.y *= wself; acc.z *= wself; acc.w *= wself;

    int b = g_rowstart[i];
    int e = g_rowstart[i + 1];
    int j = b;
    // unroll x4 for memory-level parallelism on the gathers
    for (; j + 4 <= e; j += 4) {
        int s0 = g_csr_src[j];
        int s1 = g_csr_src[j + 1];
        int s2 = g_csr_src[j + 2];
        int s3 = g_csr_src[j + 3];
        float w0 = g_csr_w[j];
        float w1 = g_csr_w[j + 1];
        float w2 = g_csr_w[j + 2];
        float w3 = g_csr_w[j + 3];
        float4 v0 = ((const float4*)&h[(size_t)s0 * 128])[lane];
        float4 v1 = ((const float4*)&h[(size_t)s1 * 128])[lane];
        float4 v2 = ((const float4*)&h[(size_t)s2 * 128])[lane];
        float4 v3 = ((const float4*)&h[(size_t)s3 * 128])[lane];
        acc.x += v0.x * w0; acc.y += v0.y * w0; acc.z += v0.z * w0; acc.w += v0.w * w0;
        acc.x += v1.x * w1; acc.y += v1.y * w1; acc.z += v1.z * w1; acc.w += v1.w * w1;
        acc.x += v2.x * w2; acc.y += v2.y * w2; acc.z += v2.z * w2; acc.w += v2.w * w2;
        acc.x += v3.x * w3; acc.y += v3.y * w3; acc.z += v3.z * w3; acc.w += v3.w * w3;
    }
    for (; j < e; j++) {
        int s   = g_csr_src[j];
        float w = g_csr_w[j];
        float4 v = ((const float4*)&h[(size_t)s * 128])[lane];
        acc.x += v.x * w;
        acc.y += v.y * w;
        acc.z += v.z * w;
        acc.w += v.w * w;
    }

    float4 bb = ((const float4*)bias)[lane];
    float4 o;
    o.x = fmaxf(acc.x + bb.x, 0.f);
    o.y = fmaxf(acc.y + bb.y, 0.f);
    o.z = fmaxf(acc.z + bb.z, 0.f);
    o.w = fmaxf(acc.w + bb.w, 0.f);
    if (res) {
        float4 rv = ((const float4*)&res[(size_t)i * 128])[lane];
        o.x += rv.x; o.y += rv.y; o.z += rv.z; o.w += rv.w;
    }
    ((float4*)&out[(size_t)i * 128])[lane] = o;
}

// ---------- host launcher ----------
extern "C" void kernel_launch(void* const* d_in, const int* in_sizes, int n_in,
                              void* d_out, int out_size) {
    const float* x  = (const float*)d_in[0];
    const int*   ei = (const int*)d_in[1];
    const float* W0 = (const float*)d_in[2];
    const float* b0 = (const float*)d_in[3];
    const float* W1 = (const float*)d_in[4];
    const float* b1 = (const float*)d_in[5];
    const float* W2 = (const float*)d_in[6];
    const float* b2 = (const float*)d_in[7];
    const float* Wr = (const float*)d_in[8];
    const float* br = (const float*)d_in[9];
    float* out = (float*)d_out;

    const int* src = ei;        // edge_index[0]
    const int* dst = ei + EE;   // edge_index[1]

    float *res_p, *h_p, *y_p;
    cudaGetSymbolAddress((void**)&res_p, g_res);
    cudaGetSymbolAddress((void**)&h_p, g_h);
    cudaGetSymbolAddress((void**)&y_p, g_y);

    const int GB = (NN + 63) / 64;        // GEMM blocks
    const int AB = (NN + 7) / 8;          // agg blocks (8 warps/block)
    const int EB = (EE + 255) / 256;
    const int NB = (NN + 255) / 256;

    // graph structure (recomputed each call; no caching)
    k_deg_init<<<NB, 256>>>();
    k_count<<<EB, 256>>>(dst);
    k_scan1<<<SCAN_NB, SCAN_TPB>>>();
    k_scan2<<<1, 128>>>();
    k_scan3<<<SCAN_NB, SCAN_TPB>>>();
    k_fill<<<EB, 256>>>(src, dst);

    // residual = x @ Wr + br
    k_gemm<<<GB, 256>>>(x, Wr, br, res_p, NN);

    // layer 0
    k_gemm<<<GB, 256>>>(x, W0, nullptr, h_p, NN);
    k_agg<<<AB, 256>>>(h_p, b0, res_p, y_p);

    // layer 1
    k_gemm<<<GB, 256>>>(y_p, W1, nullptr, h_p, NN);
    k_agg<<<AB, 256>>>(h_p, b1, nullptr, y_p);

    // layer 2
    k_gemm<<<GB, 256>>>(y_p, W2, nullptr, h_p, NN);
    k_agg<<<AB, 256>>>(h_p, b2, nullptr, out);
}